// round 12
// baseline (speedup 1.0000x reference)
#include <cuda_runtime.h>
#include <cuda_fp16.h>
#include <stdint.h>

#define SEQT 512
#define NB   8
#define NT   256

#define S0   232    // layer0 B row stride bytes (K=96 -> 6x32B groups + pad, conflict-tuned)
#define S1   296    // layer1 B row stride bytes (K=128 -> 8x32B groups + pad, conflict-tuned)

// dynamic SMEM map (bytes)
#define OFF_B0   0                      // 2 parities x 8*232 = 3712
#define OFF_B1   3712                   // 2 parities x 8*296 = 4736
#define OFF_A1S  8448                   // 8 warps x 4 kt x 2 tiles x 512B = 32768
#define SMEM_TOTAL 41216

__device__ __forceinline__ void mma_f16(float c[4], const uint32_t a[4],
                                        uint32_t b0, uint32_t b1) {
    asm volatile(
        "mma.sync.aligned.m16n8k16.row.col.f32.f16.f16.f32 "
        "{%0,%1,%2,%3}, {%4,%5,%6,%7}, {%8,%9}, {%0,%1,%2,%3};"
        : "+f"(c[0]), "+f"(c[1]), "+f"(c[2]), "+f"(c[3])
        : "r"(a[0]), "r"(a[1]), "r"(a[2]), "r"(a[3]), "r"(b0), "r"(b1));
}

__device__ __forceinline__ float tanha(float x) {
    float r; asm("tanh.approx.f32 %0, %1;" : "=f"(r) : "f"(x)); return r;
}
__device__ __forceinline__ float sigf(float x)   { return fmaf(tanha(0.5f * x), 0.5f, 0.5f); }

// byte offset of (batch n, k) in fp16 B buffer
// 32B group per 16 k; 8B unit per tq: [k(2t), k(2t+1), k(2t+8), k(2t+9)]
__device__ __forceinline__ int boff(int n, int k, int S) {
    return n * S + (k >> 4) * 32 + ((k >> 1) & 3) * 8 + ((k >> 3) & 1) * 4 + (k & 1) * 2;
}

__global__ void __launch_bounds__(NT, 2)
lstm_fused(const float* __restrict__ x,
           const float* __restrict__ W_ih0, const float* __restrict__ W_hh0,
           const float* __restrict__ b_ih0, const float* __restrict__ b_hh0,
           const float* __restrict__ W_ih1, const float* __restrict__ W_hh1,
           const float* __restrict__ b_ih1, const float* __restrict__ b_hh1,
           const float* __restrict__ ln_g, const float* __restrict__ ln_b,
           const float* __restrict__ fc_w, const float* __restrict__ fc_b,
           float* __restrict__ out)
{
    extern __shared__ __align__(16) unsigned char sm[];
    const int tid  = threadIdx.x;
    const int w    = tid >> 5;       // 8 warps; warp w owns cells jv = 8w..8w+7
    const int lane = tid & 31;
    const int g    = lane >> 2;
    const int tq   = lane & 3;
    const int jv   = 8 * w + g;      // cell index this thread owns
    const int b0   = blockIdx.x * NB;

    // zero B buffers
    for (int i = tid; i < OFF_A1S / 4; i += NT) ((uint32_t*)sm)[i] = 0;

    // ---- A fragments: full K. A0 (6 kt) + A1 kt0-3 in regs; A1 kt4-7 in SMEM ----
    uint32_t A0[2][6][4], A1r[2][4][4];
    #pragma unroll
    for (int tile = 0; tile < 2; tile++) {
        #pragma unroll
        for (int kt = 0; kt < 6; kt++) {
            #pragma unroll
            for (int i = 0; i < 4; i++) {
                int m = tile * 128 + (i & 1) * 64 + jv;
                int k = 16 * kt + 2 * tq + (i >> 1) * 8;
                float v0 = (k < 32)     ? W_ih0[m * 32 + k]     : W_hh0[m * 64 + k - 32];
                float v1 = (k + 1 < 32) ? W_ih0[m * 32 + k + 1] : W_hh0[m * 64 + k + 1 - 32];
                uint16_t h0 = __half_as_ushort(__float2half_rn(v0));
                uint16_t h1 = __half_as_ushort(__float2half_rn(v1));
                A0[tile][kt][i] = (uint32_t)h0 | ((uint32_t)h1 << 16);
            }
        }
        #pragma unroll
        for (int kt = 0; kt < 8; kt++) {
            uint32_t frag[4];
            #pragma unroll
            for (int i = 0; i < 4; i++) {
                int m = tile * 128 + (i & 1) * 64 + jv;
                int k = 16 * kt + 2 * tq + (i >> 1) * 8;
                float v0 = (k < 64)     ? W_ih1[m * 64 + k]     : W_hh1[m * 64 + k - 64];
                float v1 = (k + 1 < 64) ? W_ih1[m * 64 + k + 1] : W_hh1[m * 64 + k + 1 - 64];
                uint16_t h0 = __half_as_ushort(__float2half_rn(v0));
                uint16_t h1 = __half_as_ushort(__float2half_rn(v1));
                frag[i] = (uint32_t)h0 | ((uint32_t)h1 << 16);
            }
            if (kt < 4) {
                A1r[tile][kt][0] = frag[0]; A1r[tile][kt][1] = frag[1];
                A1r[tile][kt][2] = frag[2]; A1r[tile][kt][3] = frag[3];
            } else {
                *(uint4*)(sm + OFF_A1S + w * 4096 + (kt - 4) * 1024 + tile * 512 + lane * 16)
                    = make_uint4(frag[0], frag[1], frag[2], frag[3]);
            }
        }
    }

    float bias0[4], bias1[4];
    #pragma unroll
    for (int q = 0; q < 4; q++) {
        bias0[q] = b_ih0[q * 64 + jv] + b_hh0[q * 64 + jv];
        bias1[q] = b_ih1[q * 64 + jv] + b_hh1[q * 64 + jv];
    }

    // x(0) -> B0 parity 0 (warp = batch row, lane = k)
    {
        float xv = x[((size_t)(b0 + w) * SEQT) * 32 + lane];
        *(uint16_t*)(sm + OFF_B0 + boff(w, lane, S0)) =
            __half_as_ushort(__float2half_rn(xv));
    }
    __syncthreads();

    float c0s[2] = {0, 0}, c1s[2] = {0, 0}, h1fin[2] = {0, 0};

    // ---------- phase bodies ----------
    auto l0_mma = [&](const unsigned char* B0r, float C0[2][4]) {
        #pragma unroll
        for (int kt = 0; kt < 6; kt++) {
            uint2 v = *(const uint2*)(B0r + g * S0 + kt * 32 + tq * 8);
            mma_f16(C0[0], A0[0][kt], v.x, v.y);
            mma_f16(C0[1], A0[1][kt], v.x, v.y);
        }
    };
    auto l1_mma = [&](const unsigned char* B1r, float C1[2][4]) {
        #pragma unroll
        for (int kt = 0; kt < 4; kt++) {
            uint2 v = *(const uint2*)(B1r + g * S1 + kt * 32 + tq * 8);
            mma_f16(C1[0], A1r[0][kt], v.x, v.y);
            mma_f16(C1[1], A1r[1][kt], v.x, v.y);
        }
        #pragma unroll
        for (int kt = 4; kt < 8; kt++) {
            uint2 v = *(const uint2*)(B1r + g * S1 + kt * 32 + tq * 8);
            uint4 a0 = *(const uint4*)(sm + OFF_A1S + w * 4096 + (kt - 4) * 1024 + lane * 16);
            uint4 a1 = *(const uint4*)(sm + OFF_A1S + w * 4096 + (kt - 4) * 1024 + 512 + lane * 16);
            mma_f16(C1[0], (const uint32_t*)&a0, v.x, v.y);
            mma_f16(C1[1], (const uint32_t*)&a1, v.x, v.y);
        }
    };
    auto l0_upd = [&](const float C0[2][4], unsigned char* B0w, unsigned char* B1w) {
        #pragma unroll
        for (int d = 0; d < 2; d++) {
            float pi = C0[0][d]     + bias0[0];
            float pf = C0[0][2 + d] + bias0[1];
            float pg = C0[1][d]     + bias0[2];
            float po = C0[1][2 + d] + bias0[3];
            float ig = sigf(pi), fg = sigf(pf), gg = tanha(pg), og = sigf(po);
            float c = fg * c0s[d] + ig * gg;
            c0s[d] = c;
            float h = og * tanha(c);
            int b = 2 * tq + d;
            uint16_t hh = __half_as_ushort(__float2half_rn(h));
            *(uint16_t*)(B0w + boff(b, 32 + jv, S0)) = hh;   // layer0 recurrence
            *(uint16_t*)(B1w + boff(b, jv, S1))      = hh;   // layer1 input
        }
    };
    auto l1_upd = [&](const float C1[2][4], unsigned char* B1w) {
        #pragma unroll
        for (int d = 0; d < 2; d++) {
            float pi = C1[0][d]     + bias1[0];
            float pf = C1[0][2 + d] + bias1[1];
            float pg = C1[1][d]     + bias1[2];
            float po = C1[1][2 + d] + bias1[3];
            float ig = sigf(pi), fg = sigf(pf), gg = tanha(pg), og = sigf(po);
            float c = fg * c1s[d] + ig * gg;
            c1s[d] = c;
            float h = og * tanha(c);
            h1fin[d] = h;
            int b = 2 * tq + d;
            uint16_t hh = __half_as_ushort(__float2half_rn(h));
            *(uint16_t*)(B1w + boff(b, 64 + jv, S1)) = hh;   // layer1 recurrence
        }
    };

    // ---------- p = 0 (layer0 only) ----------
    {
        const unsigned char* B0r = sm + OFF_B0;
        unsigned char* B0w = sm + OFF_B0 + NB * S0;
        unsigned char* B1w = sm + OFF_B1 + NB * S1;
        float xn = x[((size_t)(b0 + w) * SEQT + 1) * 32 + lane];
        float C0[2][4] = {};
        l0_mma(B0r, C0);
        l0_upd(C0, B0w, B1w);
        *(uint16_t*)(B0w + boff(w, lane, S0)) = __half_as_ushort(__float2half_rn(xn));
        __syncthreads();
    }

    // ---------- main loop p = 1 .. SEQT-1 (both layers, one barrier per phase) ----------
    #pragma unroll 1
    for (int p = 1; p < SEQT; p++) {
        const int par = p & 1;
        const unsigned char* B0r = sm + OFF_B0 + par * (NB * S0);
        const unsigned char* B1r = sm + OFF_B1 + par * (NB * S1);
        unsigned char* B0w = sm + OFF_B0 + (par ^ 1) * (NB * S0);
        unsigned char* B1w = sm + OFF_B1 + (par ^ 1) * (NB * S1);

        float xn = 0.0f;
        if (p + 1 < SEQT)
            xn = x[((size_t)(b0 + w) * SEQT + (p + 1)) * 32 + lane];

        float C0[2][4] = {};
        float C1[2][4] = {};
        l0_mma(B0r, C0);
        l1_mma(B1r, C1);
        l0_upd(C0, B0w, B1w);
        l1_upd(C1, B1w);

        if (p + 1 < SEQT)
            *(uint16_t*)(B0w + boff(w, lane, S0)) = __half_as_ushort(__float2half_rn(xn));
        __syncthreads();
    }

    // ---------- p = SEQT (layer1 only, t = SEQT-1) ----------
    {
        const unsigned char* B1r = sm + OFF_B1;          // parity 0 (SEQT even)
        unsigned char* B1w = sm + OFF_B1 + NB * S1;
        float C1[2][4] = {};
        l1_mma(B1r, C1);
        l1_upd(C1, B1w);
        __syncthreads();
    }

    // ---- LayerNorm + FC on h1(T-1) ----
    float* hb = (float*)(sm + OFF_B0);    // reuse B0 area (done with it)
    #pragma unroll
    for (int d = 0; d < 2; d++) {
        int b = 2 * tq + d;
        hb[b * 64 + jv] = h1fin[d];
    }
    __syncthreads();
    if (tid < NB) {
        const float* h = hb + tid * 64;
        float mu = 0.0f;
        #pragma unroll
        for (int j = 0; j < 64; j++) mu += h[j];
        mu *= (1.0f / 64.0f);
        float var = 0.0f;
        #pragma unroll
        for (int j = 0; j < 64; j++) { float dd = h[j] - mu; var += dd * dd; }
        var *= (1.0f / 64.0f);
        float rstd = rsqrtf(var + 1e-5f);
        float sacc = 0.0f;
        #pragma unroll
        for (int j = 0; j < 64; j++)
            sacc += ((h[j] - mu) * rstd * ln_g[j] + ln_b[j]) * fc_w[j];
        out[b0 + tid] = sacc + fc_b[0];
    }
}

extern "C" void kernel_launch(void* const* d_in, const int* in_sizes, int n_in,
                              void* d_out, int out_size)
{
    const float* x     = (const float*)d_in[0];
    const float* W_ih0 = (const float*)d_in[1];
    const float* W_hh0 = (const float*)d_in[2];
    const float* b_ih0 = (const float*)d_in[3];
    const float* b_hh0 = (const float*)d_in[4];
    const float* W_ih1 = (const float*)d_in[5];
    const float* W_hh1 = (const float*)d_in[6];
    const float* b_ih1 = (const float*)d_in[7];
    const float* b_hh1 = (const float*)d_in[8];
    const float* ln_g  = (const float*)d_in[9];
    const float* ln_b  = (const float*)d_in[10];
    const float* fc_w  = (const float*)d_in[11];
    const float* fc_b  = (const float*)d_in[12];
    float* out = (float*)d_out;

    cudaFuncSetAttribute(lstm_fused, cudaFuncAttributeMaxDynamicSharedMemorySize, SMEM_TOTAL);
    lstm_fused<<<2048 / NB, NT, SMEM_TOTAL>>>(x, W_ih0, W_hh0, b_ih0, b_hh0,
                                              W_ih1, W_hh1, b_ih1, b_hh1,
                                              ln_g, ln_b, fc_w, fc_b, out);
}

// round 13
// speedup vs baseline: 1.5502x; 1.5502x over previous
#include <cuda_runtime.h>
#include <cuda_fp16.h>
#include <stdint.h>

#define SEQT 512
#define NB   16
#define NT   512

#define S0   224    // layer0 B row stride bytes (K=96 -> 6x32B groups + pad)
#define S1   288    // layer1 B row stride bytes (K=128 -> 8x32B groups + pad)

// dynamic SMEM map (bytes)
#define OFF_B0   0                      // 2 parities x 16*224 = 7168
#define OFF_B1   7168                   // 2 parities x 16*288 = 9216
#define SMEM_TOTAL 20480                // + LN scratch reuses B0

__device__ __forceinline__ void mma_f16(float c[4], const uint32_t a[4],
                                        uint32_t b0, uint32_t b1) {
    asm volatile(
        "mma.sync.aligned.m16n8k16.row.col.f32.f16.f16.f32 "
        "{%0,%1,%2,%3}, {%4,%5,%6,%7}, {%8,%9}, {%0,%1,%2,%3};"
        : "+f"(c[0]), "+f"(c[1]), "+f"(c[2]), "+f"(c[3])
        : "r"(a[0]), "r"(a[1]), "r"(a[2]), "r"(a[3]), "r"(b0), "r"(b1));
}

__device__ __forceinline__ float tanha(float x) {
    float r; asm("tanh.approx.f32 %0, %1;" : "=f"(r) : "f"(x)); return r;
}
__device__ __forceinline__ float sigf(float x) { return fmaf(tanha(0.5f * x), 0.5f, 0.5f); }

// byte offset of (batch n, k) in fp16 B buffer
// 32B group per 16 k; 8B unit per tq: [k(2t), k(2t+1), k(2t+8), k(2t+9)]
__device__ __forceinline__ int boff(int n, int k, int S) {
    return n * S + (k >> 4) * 32 + ((k >> 1) & 3) * 8 + ((k >> 3) & 1) * 4 + (k & 1) * 2;
}

__global__ void __launch_bounds__(NT, 1)
lstm_fused(const float* __restrict__ x,
           const float* __restrict__ W_ih0, const float* __restrict__ W_hh0,
           const float* __restrict__ b_ih0, const float* __restrict__ b_hh0,
           const float* __restrict__ W_ih1, const float* __restrict__ W_hh1,
           const float* __restrict__ b_ih1, const float* __restrict__ b_hh1,
           const float* __restrict__ ln_g, const float* __restrict__ ln_b,
           const float* __restrict__ fc_w, const float* __restrict__ fc_b,
           float* __restrict__ out)
{
    extern __shared__ __align__(16) unsigned char sm[];
    const int tid  = threadIdx.x;
    const int w    = tid >> 5;
    const int lane = tid & 31;
    const int g    = lane >> 2;
    const int tq   = lane & 3;
    const int role = w >> 3;          // 0: layer0 warps, 1: layer1 warps
    const int jv   = 8 * (w & 7) + g; // cell index this thread owns
    const int b0   = blockIdx.x * NB;

    // zero B buffers (both parities)
    for (int i = tid; i < 16384 / 4; i += NT) ((uint32_t*)sm)[i] = 0;

    // ---- A fragments: my layer only, full K, fp16 in regs ----
    // A[tile][kt][frag]; layer0 uses kt 0-5 (K=96), layer1 kt 0-7 (K=128)
    uint32_t A[2][8][4];
    if (role == 0) {
        #pragma unroll
        for (int tile = 0; tile < 2; tile++)
            #pragma unroll
            for (int kt = 0; kt < 6; kt++)
                #pragma unroll
                for (int i = 0; i < 4; i++) {
                    int m = tile * 128 + (i & 1) * 64 + jv;
                    int k = 16 * kt + 2 * tq + (i >> 1) * 8;
                    float v0 = (k < 32)     ? W_ih0[m * 32 + k]     : W_hh0[m * 64 + k - 32];
                    float v1 = (k + 1 < 32) ? W_ih0[m * 32 + k + 1] : W_hh0[m * 64 + k + 1 - 32];
                    uint16_t h0 = __half_as_ushort(__float2half_rn(v0));
                    uint16_t h1 = __half_as_ushort(__float2half_rn(v1));
                    A[tile][kt][i] = (uint32_t)h0 | ((uint32_t)h1 << 16);
                }
    } else {
        #pragma unroll
        for (int tile = 0; tile < 2; tile++)
            #pragma unroll
            for (int kt = 0; kt < 8; kt++)
                #pragma unroll
                for (int i = 0; i < 4; i++) {
                    int m = tile * 128 + (i & 1) * 64 + jv;
                    int k = 16 * kt + 2 * tq + (i >> 1) * 8;
                    float v0 = (k < 64)     ? W_ih1[m * 64 + k]     : W_hh1[m * 64 + k - 64];
                    float v1 = (k + 1 < 64) ? W_ih1[m * 64 + k + 1] : W_hh1[m * 64 + k + 1 - 64];
                    uint16_t h0 = __half_as_ushort(__float2half_rn(v0));
                    uint16_t h1 = __half_as_ushort(__float2half_rn(v1));
                    A[tile][kt][i] = (uint32_t)h0 | ((uint32_t)h1 << 16);
                }
    }

    float bias[4];
    #pragma unroll
    for (int q = 0; q < 4; q++) {
        bias[q] = role ? (b_ih1[q * 64 + jv] + b_hh1[q * 64 + jv])
                       : (b_ih0[q * 64 + jv] + b_hh0[q * 64 + jv]);
    }

    // x(0) -> B0 parity 0 (warp = batch row, lane = k)
    {
        float xv = x[((size_t)(b0 + w) * SEQT) * 32 + lane];
        *(uint16_t*)(sm + OFF_B0 + boff(w, lane, S0)) =
            __half_as_ushort(__float2half_rn(xv));
    }
    __syncthreads();

    float cs[2][2] = {{0, 0}, {0, 0}};          // my layer's c-state [nt][d]
    float h1fin[2][2] = {{0, 0}, {0, 0}};       // layer1 warps: final h

    // ---------- role bodies ----------
    auto l0_phase = [&](const unsigned char* B0r, unsigned char* B0w, unsigned char* B1w) {
        float C[2][2][4] = {};                  // [tile][nt][2r+d]
        #pragma unroll
        for (int kt = 0; kt < 6; kt++) {
            #pragma unroll
            for (int nt = 0; nt < 2; nt++) {
                uint2 v = *(const uint2*)(B0r + (8 * nt + g) * S0 + kt * 32 + tq * 8);
                mma_f16(C[0][nt], A[0][kt], v.x, v.y);
                mma_f16(C[1][nt], A[1][kt], v.x, v.y);
            }
        }
        #pragma unroll
        for (int nt = 0; nt < 2; nt++)
            #pragma unroll
            for (int d = 0; d < 2; d++) {
                float pi = C[0][nt][d]     + bias[0];
                float pf = C[0][nt][2 + d] + bias[1];
                float pg = C[1][nt][d]     + bias[2];
                float po = C[1][nt][2 + d] + bias[3];
                float ig = sigf(pi), fg = sigf(pf), gg = tanha(pg), og = sigf(po);
                float c = fg * cs[nt][d] + ig * gg;
                cs[nt][d] = c;
                float h = og * tanha(c);
                int b = 8 * nt + 2 * tq + d;
                uint16_t hh = __half_as_ushort(__float2half_rn(h));
                *(uint16_t*)(B0w + boff(b, 32 + jv, S0)) = hh;   // layer0 recurrence
                *(uint16_t*)(B1w + boff(b, jv, S1))      = hh;   // layer1 input
            }
    };
    auto l1_phase = [&](const unsigned char* B1r, unsigned char* B1w) {
        float C[2][2][4] = {};
        #pragma unroll
        for (int kt = 0; kt < 8; kt++) {
            #pragma unroll
            for (int nt = 0; nt < 2; nt++) {
                uint2 v = *(const uint2*)(B1r + (8 * nt + g) * S1 + kt * 32 + tq * 8);
                mma_f16(C[0][nt], A[0][kt], v.x, v.y);
                mma_f16(C[1][nt], A[1][kt], v.x, v.y);
            }
        }
        #pragma unroll
        for (int nt = 0; nt < 2; nt++)
            #pragma unroll
            for (int d = 0; d < 2; d++) {
                float pi = C[0][nt][d]     + bias[0];
                float pf = C[0][nt][2 + d] + bias[1];
                float pg = C[1][nt][d]     + bias[2];
                float po = C[1][nt][2 + d] + bias[3];
                float ig = sigf(pi), fg = sigf(pf), gg = tanha(pg), og = sigf(po);
                float c = fg * cs[nt][d] + ig * gg;
                cs[nt][d] = c;
                float h = og * tanha(c);
                h1fin[nt][d] = h;
                int b = 8 * nt + 2 * tq + d;
                uint16_t hh = __half_as_ushort(__float2half_rn(h));
                *(uint16_t*)(B1w + boff(b, 64 + jv, S1)) = hh;   // layer1 recurrence
            }
    };

    // ---------- p = 0 (layer0 warps only) ----------
    {
        float xn = x[((size_t)(b0 + w) * SEQT + 1) * 32 + lane];
        if (role == 0)
            l0_phase(sm + OFF_B0, sm + OFF_B0 + NB * S0, sm + OFF_B1 + NB * S1);
        *(uint16_t*)(sm + OFF_B0 + NB * S0 + boff(w, lane, S0)) =
            __half_as_ushort(__float2half_rn(xn));
        __syncthreads();
    }

    // ---------- main loop p = 1 .. SEQT-1 ----------
    #pragma unroll 1
    for (int p = 1; p < SEQT; p++) {
        const int par = p & 1;
        const unsigned char* B0r = sm + OFF_B0 + par * (NB * S0);
        const unsigned char* B1r = sm + OFF_B1 + par * (NB * S1);
        unsigned char* B0w = sm + OFF_B0 + (par ^ 1) * (NB * S0);
        unsigned char* B1w = sm + OFF_B1 + (par ^ 1) * (NB * S1);

        float xn = 0.0f;
        if (p + 1 < SEQT)
            xn = x[((size_t)(b0 + w) * SEQT + (p + 1)) * 32 + lane];

        if (role == 0)
            l0_phase(B0r, B0w, B1w);
        else
            l1_phase(B1r, B1w);

        if (p + 1 < SEQT)
            *(uint16_t*)(B0w + boff(w, lane, S0)) = __half_as_ushort(__float2half_rn(xn));
        __syncthreads();
    }

    // ---------- p = SEQT (layer1 warps only, t = SEQT-1) ----------
    {
        if (role == 1)
            l1_phase(sm + OFF_B1, sm + OFF_B1 + NB * S1);   // parity 0 (SEQT even)
        __syncthreads();
    }

    // ---- LayerNorm + FC on h1(T-1) ----
    float* hb = (float*)(sm + OFF_B0);    // reuse B0 area
    if (role == 1) {
        #pragma unroll
        for (int nt = 0; nt < 2; nt++)
            #pragma unroll
            for (int d = 0; d < 2; d++) {
                int b = 8 * nt + 2 * tq + d;
                hb[b * 64 + jv] = h1fin[nt][d];
            }
    }
    __syncthreads();
    if (tid < NB) {
        const float* h = hb + tid * 64;
        float mu = 0.0f;
        #pragma unroll
        for (int j = 0; j < 64; j++) mu += h[j];
        mu *= (1.0f / 64.0f);
        float var = 0.0f;
        #pragma unroll
        for (int j = 0; j < 64; j++) { float dd = h[j] - mu; var += dd * dd; }
        var *= (1.0f / 64.0f);
        float rstd = rsqrtf(var + 1e-5f);
        float sacc = 0.0f;
        #pragma unroll
        for (int j = 0; j < 64; j++)
            sacc += ((h[j] - mu) * rstd * ln_g[j] + ln_b[j]) * fc_w[j];
        out[b0 + tid] = sacc + fc_b[0];
    }
}

extern "C" void kernel_launch(void* const* d_in, const int* in_sizes, int n_in,
                              void* d_out, int out_size)
{
    const float* x     = (const float*)d_in[0];
    const float* W_ih0 = (const float*)d_in[1];
    const float* W_hh0 = (const float*)d_in[2];
    const float* b_ih0 = (const float*)d_in[3];
    const float* b_hh0 = (const float*)d_in[4];
    const float* W_ih1 = (const float*)d_in[5];
    const float* W_hh1 = (const float*)d_in[6];
    const float* b_ih1 = (const float*)d_in[7];
    const float* b_hh1 = (const float*)d_in[8];
    const float* ln_g  = (const float*)d_in[9];
    const float* ln_b  = (const float*)d_in[10];
    const float* fc_w  = (const float*)d_in[11];
    const float* fc_b  = (const float*)d_in[12];
    float* out = (float*)d_out;

    cudaFuncSetAttribute(lstm_fused, cudaFuncAttributeMaxDynamicSharedMemorySize, SMEM_TOTAL);
    lstm_fused<<<2048 / NB, NT, SMEM_TOTAL>>>(x, W_ih0, W_hh0, b_ih0, b_hh0,
                                              W_ih1, W_hh1, b_ih1, b_hh1,
                                              ln_g, ln_b, fc_w, fc_b, out);
}